// round 1
// baseline (speedup 1.0000x reference)
#include <cuda_runtime.h>

#define Bn 32
#define Sn 512
#define In 1024
#define Hn 1024
#define Ln 3
#define On 1024
#define NCTA 128
#define NTHR 256

typedef unsigned long long ull;

// Scratch: double-buffered hidden state per layer (graph-replay safe: fully
// rewritten each launch starting from h0).
__device__ float g_hbuf[2][Ln][Bn][Hn];
__device__ unsigned g_cnt = 0;
__device__ unsigned g_gen = 0;

// ---------------- packed f32x2 helpers ----------------
__device__ __forceinline__ void ffma2(ull& acc, float w, ull in) {
    ull wp;
    asm("mov.b64 %0, {%1, %1};" : "=l"(wp) : "f"(w));
    asm("fma.rn.f32x2 %0, %1, %2, %0;" : "+l"(acc) : "l"(wp), "l"(in));
}
__device__ __forceinline__ float2 u2f(ull v) {
    float2 r;
    asm("mov.b64 {%0, %1}, %2;" : "=f"(r.x), "=f"(r.y) : "l"(v));
    return r;
}
__device__ __forceinline__ float2 f2add(float2 a, float2 b) {
    return make_float2(a.x + b.x, a.y + b.y);
}

// ---------------- software grid barrier ----------------
__device__ __forceinline__ void gsync() {
    __threadfence();
    __syncthreads();
    if (threadIdx.x == 0) {
        unsigned gen = *((volatile unsigned*)&g_gen);
        unsigned t = atomicAdd(&g_cnt, 1u);
        if (t == gridDim.x - 1) {
            g_cnt = 0;
            __threadfence();
            *((volatile unsigned*)&g_gen) = gen + 1;
        } else {
            while (*((volatile unsigned*)&g_gen) == gen) { }
        }
        __threadfence();
    }
    __syncthreads();
}

// Load one K-tile (128 per khalf, both halves) of the input activation matrix
// into shared, pre-paired as float2(v[b], v[b+16]).
// shIn[kh][kk][bp] ; padded to 17 to kill write bank conflicts.
__device__ __forceinline__ void load_tile(float2 shIn[2][128][17],
                                          const float* __restrict__ src,
                                          size_t stride, int tile) {
    int tid = threadIdx.x;
#pragma unroll
    for (int rep = 0; rep < 8; ++rep) {
        int i4 = tid + rep * 256;       // 0..2047 float4 units
        int b_ = i4 >> 6;               // 0..31
        int r  = i4 & 63;
        int kh_ = r >> 5;               // 0..1
        int qq  = r & 31;               // 0..31 (float4 within 128-wide tile)
        int k = kh_ * 512 + tile * 128 + qq * 4;
        float4 v = *reinterpret_cast<const float4*>(src + (size_t)b_ * stride + k);
        int bp_ = b_ & 15, hi = b_ >> 4;
        reinterpret_cast<float*>(&shIn[kh_][qq * 4 + 0][bp_])[hi] = v.x;
        reinterpret_cast<float*>(&shIn[kh_][qq * 4 + 1][bp_])[hi] = v.y;
        reinterpret_cast<float*>(&shIn[kh_][qq * 4 + 2][bp_])[hi] = v.z;
        reinterpret_cast<float*>(&shIn[kh_][qq * 4 + 3][bp_])[hi] = v.w;
    }
}

// Accumulate 3 gate dot-products over K=1024 (this thread covers its khalf=512).
__device__ __forceinline__ void mm3(float2 shIn[2][128][17],
                                    const float* __restrict__ w0,
                                    const float* __restrict__ w1,
                                    const float* __restrict__ w2,
                                    const float* __restrict__ src, size_t stride,
                                    int n, int kh, int bp,
                                    ull& a0, ull& a1, ull& a2) {
    const float* p0 = w0 + (size_t)n * 1024 + kh * 512;
    const float* p1 = w1 + (size_t)n * 1024 + kh * 512;
    const float* p2 = w2 + (size_t)n * 1024 + kh * 512;
    for (int tile = 0; tile < 4; ++tile) {
        __syncthreads();
        load_tile(shIn, src, stride, tile);
        __syncthreads();
        const float* q0 = p0 + tile * 128;
        const float* q1 = p1 + tile * 128;
        const float* q2 = p2 + tile * 128;
#pragma unroll 8
        for (int kk = 0; kk < 128; kk += 4) {
            float4 v0 = *reinterpret_cast<const float4*>(q0 + kk);
            float4 v1 = *reinterpret_cast<const float4*>(q1 + kk);
            float4 v2 = *reinterpret_cast<const float4*>(q2 + kk);
            ull i0 = *reinterpret_cast<ull*>(&shIn[kh][kk + 0][bp]);
            ull i1 = *reinterpret_cast<ull*>(&shIn[kh][kk + 1][bp]);
            ull i2 = *reinterpret_cast<ull*>(&shIn[kh][kk + 2][bp]);
            ull i3 = *reinterpret_cast<ull*>(&shIn[kh][kk + 3][bp]);
            ffma2(a0, v0.x, i0); ffma2(a0, v0.y, i1); ffma2(a0, v0.z, i2); ffma2(a0, v0.w, i3);
            ffma2(a1, v1.x, i0); ffma2(a1, v1.y, i1); ffma2(a1, v1.z, i2); ffma2(a1, v1.w, i3);
            ffma2(a2, v2.x, i0); ffma2(a2, v2.y, i1); ffma2(a2, v2.z, i2); ffma2(a2, v2.w, i3);
        }
    }
}

// Single-stream variant (output projection).
__device__ __forceinline__ void mm1(float2 shIn[2][128][17],
                                    const float* __restrict__ w0,
                                    const float* __restrict__ src, size_t stride,
                                    int n, int kh, int bp, ull& a0) {
    const float* p0 = w0 + (size_t)n * 1024 + kh * 512;
    for (int tile = 0; tile < 4; ++tile) {
        __syncthreads();
        load_tile(shIn, src, stride, tile);
        __syncthreads();
        const float* q0 = p0 + tile * 128;
#pragma unroll 8
        for (int kk = 0; kk < 128; kk += 4) {
            float4 v0 = *reinterpret_cast<const float4*>(q0 + kk);
            ull i0 = *reinterpret_cast<ull*>(&shIn[kh][kk + 0][bp]);
            ull i1 = *reinterpret_cast<ull*>(&shIn[kh][kk + 1][bp]);
            ull i2 = *reinterpret_cast<ull*>(&shIn[kh][kk + 2][bp]);
            ull i3 = *reinterpret_cast<ull*>(&shIn[kh][kk + 3][bp]);
            ffma2(a0, v0.x, i0); ffma2(a0, v0.y, i1); ffma2(a0, v0.z, i2); ffma2(a0, v0.w, i3);
        }
    }
}

__global__ void __launch_bounds__(NTHR, 1)
gru_persistent(const float* __restrict__ x, const float* __restrict__ h0,
               const float* __restrict__ Wzi, const float* __restrict__ Wzh,
               const float* __restrict__ bzh, const float* __restrict__ Wri,
               const float* __restrict__ Wrh, const float* __restrict__ brh,
               const float* __restrict__ Wgi, const float* __restrict__ Wgh,
               const float* __restrict__ bgh, const float* __restrict__ Wout,
               const float* __restrict__ bout, float* __restrict__ out) {
    __shared__ float2 shIn[2][128][17];
    __shared__ ull shRed[128][4];

    const int tid = threadIdx.x;
    const int bp = tid & 15;          // batch pair id: batches (bp, bp+16)
    const int cs = (tid >> 4) & 7;    // column slot within CTA
    const int kh = tid >> 7;          // K-half
    const int n = blockIdx.x * 8 + cs;  // global column (0..1023)

    // init hidden buffer 0 from h0 (B, L, H) -> g_hbuf[0][l][b][h]
    for (int i = blockIdx.x * NTHR + tid; i < Ln * Bn * Hn; i += NCTA * NTHR) {
        int hh = i % Hn;
        int b_ = (i / Hn) % Bn;
        int l_ = i / (Hn * Bn);
        g_hbuf[0][l_][b_][hh] = h0[((size_t)b_ * Ln + l_) * Hn + hh];
    }
    gsync();

    int p = 0;
    for (int t = 0; t < Sn; ++t) {
        const int q = p ^ 1;
        for (int l = 0; l < Ln; ++l) {
            const float* src_in = (l == 0) ? (x + (size_t)t * In)
                                           : &g_hbuf[q][l - 1][0][0];
            const size_t stride_in = (l == 0) ? (size_t)Sn * In : (size_t)Hn;
            const float* src_h = &g_hbuf[p][l][0][0];
            const size_t wl = (size_t)l * Hn * In;

            ull az = 0, ar = 0, agi = 0, agh = 0;
            mm3(shIn, Wzi + wl, Wri + wl, Wgi + wl, src_in, stride_in, n, kh, bp,
                az, ar, agi);
            mm3(shIn, Wzh + wl, Wrh + wl, Wgh + wl, src_h, Hn, n, kh, bp,
                az, ar, agh);

            __syncthreads();
            if (kh == 1) {
                shRed[tid - 128][0] = az;
                shRed[tid - 128][1] = ar;
                shRed[tid - 128][2] = agi;
                shRed[tid - 128][3] = agh;
            }
            __syncthreads();
            if (kh == 0) {
                float2 AZ = f2add(u2f(az), u2f(shRed[tid][0]));
                float2 AR = f2add(u2f(ar), u2f(shRed[tid][1]));
                float2 AGI = f2add(u2f(agi), u2f(shRed[tid][2]));
                float2 AGH = f2add(u2f(agh), u2f(shRed[tid][3]));
                const float bz = bzh[l * Hn + n];
                const float br = brh[l * Hn + n];
                const float bg = bgh[l * Hn + n];
#pragma unroll
                for (int j = 0; j < 2; ++j) {
                    const int b = bp + j * 16;
                    float azv = (j ? AZ.y : AZ.x) + bz;
                    float arv = (j ? AR.y : AR.x) + br;
                    float agiv = (j ? AGI.y : AGI.x);
                    float aghv = (j ? AGH.y : AGH.x) + bg;
                    float zg = 1.0f / (1.0f + expf(-azv));
                    float rg = 1.0f / (1.0f + expf(-arv));
                    float gg = tanhf(agiv + rg * aghv);
                    float hold = g_hbuf[p][l][b][n];
                    g_hbuf[q][l][b][n] = zg * hold + (1.0f - zg) * gg;
                }
            }
            gsync();
        }

        // output projection for this timestep (reads g_hbuf[q][L-1], stable)
        {
            ull ao = 0;
            mm1(shIn, Wout, &g_hbuf[q][Ln - 1][0][0], Hn, n, kh, bp, ao);
            __syncthreads();
            if (kh == 1) shRed[tid - 128][0] = ao;
            __syncthreads();
            if (kh == 0) {
                float2 AO = f2add(u2f(ao), u2f(shRed[tid][0]));
                const float bo = bout[n];
                out[((size_t)bp * Sn + t) * On + n] = AO.x + bo;
                out[((size_t)(bp + 16) * Sn + t) * On + n] = AO.y + bo;
            }
            // no grid sync needed: next phase writes only g_hbuf[p][0],
            // whose readers all finished before the L0 barrier of this step.
        }
        p = q;
    }

    gsync();
    // final hidden state: out[B*S*O + (b*L + l)*H + h] = h_final
    const size_t base = (size_t)Bn * Sn * On;
    for (int i = blockIdx.x * NTHR + tid; i < Ln * Bn * Hn; i += NCTA * NTHR) {
        int hh = i % Hn;
        int b_ = (i / Hn) % Bn;
        int l_ = i / (Hn * Bn);
        out[base + ((size_t)b_ * Ln + l_) * Hn + hh] = g_hbuf[p][l_][b_][hh];
    }
}

extern "C" void kernel_launch(void* const* d_in, const int* in_sizes, int n_in,
                              void* d_out, int out_size) {
    const float* x    = (const float*)d_in[0];
    const float* h0   = (const float*)d_in[1];
    const float* Wzi  = (const float*)d_in[2];
    const float* Wzh  = (const float*)d_in[3];
    const float* bzh  = (const float*)d_in[4];
    const float* Wri  = (const float*)d_in[5];
    const float* Wrh  = (const float*)d_in[6];
    const float* brh  = (const float*)d_in[7];
    const float* Wgi  = (const float*)d_in[8];
    const float* Wgh  = (const float*)d_in[9];
    const float* bgh  = (const float*)d_in[10];
    const float* Wout = (const float*)d_in[11];
    const float* bout = (const float*)d_in[12];
    float* out = (float*)d_out;

    gru_persistent<<<NCTA, NTHR>>>(x, h0, Wzi, Wzh, bzh, Wri, Wrh, brh,
                                   Wgi, Wgh, bgh, Wout, bout, out);
}